// round 1
// baseline (speedup 1.0000x reference)
#include <cuda_runtime.h>
#include <math.h>

// Problem constants
constexpr int Bb = 4;
constexpr int NS = 2048;
constexpr int Cc = 1024;
constexpr int Hh = 16;
constexpr int HD = 64;
constexpr float SCALE = 0.125f;  // 64^-0.5

// Scratch (static device arrays; allocation inside kernel_launch is forbidden)
__device__ float g_q[Bb * Hh * NS * HD];
__device__ float g_k[Bb * Hh * NS * HD];
__device__ float g_v[Bb * Hh * NS * HD];
__device__ float g_attn[Bb * NS * Cc];

// ---------------------------------------------------------------------------
// SGEMM: C[r][d] = sum_c A[r][c] * W[d][c]  (+ bias[d])
// A: [M,K] row-major, W: [Ncol,K] row-major (K contiguous in both).
// MODE 0: QKV — scatter outputs into g_q/g_k/g_v as [B,H,N,HD]
// MODE 1: plain row-major output + bias (A==nullptr means read g_attn)
// Tiling: 128x128x16, 256 threads, 8x8 per-thread microtile.
// ---------------------------------------------------------------------------
template <int MODE>
__global__ __launch_bounds__(256, 2)
void sgemm_kernel(const float* __restrict__ A, const float* __restrict__ W,
                  const float* __restrict__ bias, float* __restrict__ Cout,
                  int M, int Ncol, int K)
{
    __shared__ float As[16][128];
    __shared__ float Bs[16][128];

    const int tid = threadIdx.x;
    const int tx = tid & 15;       // 0..15 -> output col group
    const int ty = tid >> 4;       // 0..15 -> output row group
    const int bm = blockIdx.y * 128;
    const int bn = blockIdx.x * 128;
    const int loadRow = tid >> 2;        // 0..63
    const int loadK   = (tid & 3) << 2;  // 0,4,8,12

    if (MODE == 1 && A == nullptr) A = g_attn;

    float acc[8][8];
#pragma unroll
    for (int i = 0; i < 8; ++i)
#pragma unroll
        for (int j = 0; j < 8; ++j) acc[i][j] = 0.f;

    for (int k0 = 0; k0 < K; k0 += 16) {
#pragma unroll
        for (int r = 0; r < 2; ++r) {
            const int row = loadRow + (r << 6);
            float4 a = *(const float4*)(A + (size_t)(bm + row) * K + k0 + loadK);
            As[loadK + 0][row] = a.x;
            As[loadK + 1][row] = a.y;
            As[loadK + 2][row] = a.z;
            As[loadK + 3][row] = a.w;
            float4 b = *(const float4*)(W + (size_t)(bn + row) * K + k0 + loadK);
            Bs[loadK + 0][row] = b.x;
            Bs[loadK + 1][row] = b.y;
            Bs[loadK + 2][row] = b.z;
            Bs[loadK + 3][row] = b.w;
        }
        __syncthreads();
#pragma unroll
        for (int kk = 0; kk < 16; ++kk) {
            float4 a0 = *(const float4*)&As[kk][ty * 8];
            float4 a1 = *(const float4*)&As[kk][ty * 8 + 4];
            float4 b0 = *(const float4*)&Bs[kk][tx * 8];
            float4 b1 = *(const float4*)&Bs[kk][tx * 8 + 4];
            float av[8] = {a0.x, a0.y, a0.z, a0.w, a1.x, a1.y, a1.z, a1.w};
            float bv[8] = {b0.x, b0.y, b0.z, b0.w, b1.x, b1.y, b1.z, b1.w};
#pragma unroll
            for (int i = 0; i < 8; ++i)
#pragma unroll
                for (int j = 0; j < 8; ++j)
                    acc[i][j] += av[i] * bv[j];
        }
        __syncthreads();
    }

    if (MODE == 0) {
        // QKV scatter: col d in [0,3C); which = d/C, h = (d%C)/HD, hd = d%HD
        const int which = bn >> 10;                 // constant per block
        float* dstbuf = (which == 0) ? g_q : (which == 1) ? g_k : g_v;
#pragma unroll
        for (int i = 0; i < 8; ++i) {
            const int r = bm + ty * 8 + i;
            const int b = r >> 11;        // / NS
            const int n = r & (NS - 1);
#pragma unroll
            for (int j4 = 0; j4 < 2; ++j4) {
                const int dcol = bn + tx * 8 + j4 * 4;
                const int rem = dcol & (Cc - 1);
                const int h = rem >> 6;
                const int hd = rem & (HD - 1);
                float* p = dstbuf + (size_t)((b * Hh + h) * NS + n) * HD + hd;
                float4 v;
                v.x = acc[i][j4 * 4 + 0];
                v.y = acc[i][j4 * 4 + 1];
                v.z = acc[i][j4 * 4 + 2];
                v.w = acc[i][j4 * 4 + 3];
                *(float4*)p = v;
            }
        }
    } else {
#pragma unroll
        for (int i = 0; i < 8; ++i) {
            const int r = bm + ty * 8 + i;
            float* p = Cout + (size_t)r * Ncol + bn + tx * 8;
#pragma unroll
            for (int j4 = 0; j4 < 2; ++j4) {
                const int dcol = bn + tx * 8 + j4 * 4;
                float4 v;
                v.x = acc[i][j4 * 4 + 0] + bias[dcol + 0];
                v.y = acc[i][j4 * 4 + 1] + bias[dcol + 1];
                v.z = acc[i][j4 * 4 + 2] + bias[dcol + 2];
                v.w = acc[i][j4 * 4 + 3] + bias[dcol + 3];
                *(float4*)(p + j4 * 4) = v;
            }
        }
    }
}

// ---------------------------------------------------------------------------
// Flash attention, fp32. One thread per query row (BQ=128 rows / 128 threads).
// K/V tiles (BKV=16 rows) staged in shared; broadcast LDS reads in the inner
// loops (j uniform across the warp). Online softmax with per-tile rescale.
// Writes directly into g_attn in [B, N, H*HD] layout for the proj GEMM.
// ---------------------------------------------------------------------------
__global__ __launch_bounds__(128, 2)
void attn_kernel(const float* __restrict__ mWin)
{
    constexpr int BQ = 128;
    constexpr int BKV = 16;

    __shared__ float Ks[BKV][HD];
    __shared__ float Vs[BKV][HD];
    __shared__ float biasS[BKV];

    const int bh = blockIdx.y;         // b*H + h
    const int b = bh >> 4;             // / Hh
    const int h = bh & (Hh - 1);
    const int q = blockIdx.x * BQ + threadIdx.x;

    // q row into registers, pre-scaled
    float qreg[HD];
    {
        const float* qp = g_q + (size_t)(bh * NS + q) * HD;
#pragma unroll
        for (int d4 = 0; d4 < HD / 4; ++d4) {
            float4 t = *(const float4*)(qp + 4 * d4);
            qreg[4 * d4 + 0] = t.x * SCALE;
            qreg[4 * d4 + 1] = t.y * SCALE;
            qreg[4 * d4 + 2] = t.z * SCALE;
            qreg[4 * d4 + 3] = t.w * SCALE;
        }
    }

    float o[HD];
#pragma unroll
    for (int d = 0; d < HD; ++d) o[d] = 0.f;
    float m = -INFINITY;
    float l = 0.f;

    const float* kbase = g_k + (size_t)bh * NS * HD;
    const float* vbase = g_v + (size_t)bh * NS * HD;

    for (int kv0 = 0; kv0 < NS; kv0 += BKV) {
        __syncthreads();
        // cooperative tile load (coalesced): BKV*HD = 1024 floats = 256 float4
        {
            const float4* ksrc = (const float4*)(kbase + (size_t)kv0 * HD);
            const float4* vsrc = (const float4*)(vbase + (size_t)kv0 * HD);
            float4* kdst = (float4*)&Ks[0][0];
            float4* vdst = (float4*)&Vs[0][0];
#pragma unroll
            for (int it = 0; it < (BKV * HD / 4) / 128; ++it) {
                const int i = threadIdx.x + it * 128;
                kdst[i] = ksrc[i];
                vdst[i] = vsrc[i];
            }
            if (threadIdx.x < BKV)
                biasS[threadIdx.x] =
                    mWin[b * NS + kv0 + threadIdx.x] * 100.f - 100.f;
        }
        __syncthreads();

        // scores for this tile
        float s[BKV];
#pragma unroll
        for (int j = 0; j < BKV; ++j) {
            float s0 = 0.f, s1 = 0.f, s2 = 0.f, s3 = 0.f;
#pragma unroll
            for (int d4 = 0; d4 < HD / 4; ++d4) {
                float4 k4 = *(const float4*)&Ks[j][4 * d4];
                s0 += qreg[4 * d4 + 0] * k4.x;
                s1 += qreg[4 * d4 + 1] * k4.y;
                s2 += qreg[4 * d4 + 2] * k4.z;
                s3 += qreg[4 * d4 + 3] * k4.w;
            }
            s[j] = (s0 + s1) + (s2 + s3) + biasS[j];
        }

        // online softmax: tile max, rescale, accumulate
        float tmax = m;
#pragma unroll
        for (int j = 0; j < BKV; ++j) tmax = fmaxf(tmax, s[j]);
        const float corr = __expf(m - tmax);   // m=-inf first tile -> 0
        m = tmax;
        l *= corr;
#pragma unroll
        for (int d = 0; d < HD; ++d) o[d] *= corr;

#pragma unroll
        for (int j = 0; j < BKV; ++j) {
            const float p = __expf(s[j] - m);
            l += p;
#pragma unroll
            for (int d4 = 0; d4 < HD / 4; ++d4) {
                float4 v4 = *(const float4*)&Vs[j][4 * d4];
                o[4 * d4 + 0] += p * v4.x;
                o[4 * d4 + 1] += p * v4.y;
                o[4 * d4 + 2] += p * v4.z;
                o[4 * d4 + 3] += p * v4.w;
            }
        }
    }

    const float inv = 1.f / l;
    float* outp = g_attn + (size_t)(b * NS + q) * Cc + h * HD;
#pragma unroll
    for (int d4 = 0; d4 < HD / 4; ++d4) {
        float4 v;
        v.x = o[4 * d4 + 0] * inv;
        v.y = o[4 * d4 + 1] * inv;
        v.z = o[4 * d4 + 2] * inv;
        v.w = o[4 * d4 + 3] * inv;
        *(float4*)(outp + 4 * d4) = v;
    }
}

// ---------------------------------------------------------------------------
// Launch: QKV GEMM -> attention -> proj GEMM (+bias)
// Inputs (metadata order): x[B,N,C], mWin[B,N,1], w_qkv[3C,C], w_proj[C,C],
//                          b_proj[C]. Output: fp32 [B,N,C].
// ---------------------------------------------------------------------------
extern "C" void kernel_launch(void* const* d_in, const int* in_sizes, int n_in,
                              void* d_out, int out_size)
{
    const float* x      = (const float*)d_in[0];
    const float* mWin   = (const float*)d_in[1];
    const float* w_qkv  = (const float*)d_in[2];
    const float* w_proj = (const float*)d_in[3];
    const float* b_proj = (const float*)d_in[4];
    float* out = (float*)d_out;

    // QKV projection: M=8192, N=3072, K=1024
    sgemm_kernel<0><<<dim3(3 * Cc / 128, Bb * NS / 128), 256>>>(
        x, w_qkv, nullptr, nullptr, Bb * NS, 3 * Cc, Cc);

    // Attention: grid (N/128 q-tiles, B*H heads)
    attn_kernel<<<dim3(NS / 128, Bb * Hh), 128>>>(mWin);

    // Output projection: M=8192, N=1024, K=1024, + bias
    sgemm_kernel<1><<<dim3(Cc / 128, Bb * NS / 128), 256>>>(
        nullptr, w_proj, b_proj, out, Bb * NS, Cc, Cc);
}

// round 5
// speedup vs baseline: 3.2000x; 3.2000x over previous
#include <cuda_runtime.h>
#include <cstdint>
#include <math.h>

// Problem constants
constexpr int Bb = 4;
constexpr int NS = 2048;
constexpr int Cc = 1024;
constexpr int Hh = 16;
constexpr int HD = 64;
constexpr float SCALE = 0.125f;  // 64^-0.5

// Scratch (static device arrays; allocation inside kernel_launch is forbidden)
__device__ float g_q[Bb * Hh * NS * HD];
__device__ float g_k[Bb * Hh * NS * HD];
__device__ float g_v[Bb * Hh * NS * HD];
__device__ float g_attn[Bb * NS * Cc];

// ---------------------------------------------------------------------------
// Helpers: tf32 mma.sync (sm_80+ baseline ISA — valid on plain sm_100 target)
// ---------------------------------------------------------------------------
__device__ __forceinline__ uint32_t f2tf(float f) {
    uint32_t u;
    asm("cvt.rna.tf32.f32 %0, %1;" : "=r"(u) : "f"(f));
    return u;
}

// D(16x8,f32) += A(16x8 tf32,row) * B(8x8 tf32,col)
__device__ __forceinline__ void mma_tf32(float c[4], const uint32_t a[4],
                                         const uint32_t b[2]) {
    asm volatile(
        "mma.sync.aligned.m16n8k8.row.col.f32.tf32.tf32.f32 "
        "{%0,%1,%2,%3}, {%4,%5,%6,%7}, {%8,%9}, {%0,%1,%2,%3};"
        : "+f"(c[0]), "+f"(c[1]), "+f"(c[2]), "+f"(c[3])
        : "r"(a[0]), "r"(a[1]), "r"(a[2]), "r"(a[3]), "r"(b[0]), "r"(b[1]));
}

#define CP_ASYNC16(dst_u32, src_ptr) \
    asm volatile("cp.async.cg.shared.global [%0], [%1], 16;" \
                 :: "r"(dst_u32), "l"(src_ptr))
#define CP_COMMIT() asm volatile("cp.async.commit_group;" ::: "memory")
#define CP_WAIT1() asm volatile("cp.async.wait_group 1;" ::: "memory")
#define CP_WAIT0() asm volatile("cp.async.wait_group 0;" ::: "memory")

__device__ __forceinline__ uint32_t smem_u32(const void* p) {
    uint32_t a;
    asm("{ .reg .u64 t; cvta.to.shared.u64 t, %1; cvt.u32.u64 %0, t; }"
        : "=r"(a) : "l"(p));
    return a;
}

// ---------------------------------------------------------------------------
// TF32 mma.sync GEMM: D[r][d] = sum_c A[r][c] * W[d][c]  (+ bias)
// A:[M,K] row-major, W:[Ncol,K] row-major. CTA tile 128x128x16, 8 warps,
// warp tile 64(M)x32(N). cp.async double-buffered smem, padded stride 20.
// MODE 0: scatter into g_q/g_k/g_v as [B,H,N,HD].  MODE 1: row-major + bias.
// ---------------------------------------------------------------------------
constexpr int SA = 20;   // padded smem row stride (floats)

template <int MODE>
__global__ __launch_bounds__(256)
void tgemm_kernel(const float* __restrict__ A, const float* __restrict__ W,
                  const float* __restrict__ bias, float* __restrict__ Cout,
                  int M, int Ncol, int K)
{
    __shared__ float As[2][128 * SA];
    __shared__ float Bs[2][128 * SA];

    const int tid = threadIdx.x;
    const int wid = tid >> 5, lane = tid & 31;
    const int wm = (wid & 1) * 64;   // warp M offset in tile
    const int wn = (wid >> 1) * 32;  // warp N offset in tile
    const int lr = lane >> 2;        // 0..7
    const int lc = lane & 3;         // 0..3
    const int bm = blockIdx.y * 128, bn = blockIdx.x * 128;

    if (MODE == 1 && A == nullptr) A = g_attn;
    const float* Ab = A + (size_t)bm * K;
    const float* Wb = W + (size_t)bn * K;

    const uint32_t sA0 = smem_u32(&As[0][0]);
    const uint32_t sB0 = smem_u32(&Bs[0][0]);

    // loader: 128 rows x 16 floats (= 512 float4) per operand; 2 float4/thread
    auto load_tile = [&](int kb, int buf) {
        const int k0 = kb * 16;
        const uint32_t da = sA0 + buf * (128 * SA * 4);
        const uint32_t db = sB0 + buf * (128 * SA * 4);
#pragma unroll
        for (int it = 0; it < 2; ++it) {
            const int idx = tid + it * 256;       // 0..511
            const int row = idx >> 2, q = idx & 3;
            const uint32_t so = (uint32_t)(row * SA + q * 4) * 4;
            CP_ASYNC16(da + so, Ab + (size_t)row * K + k0 + q * 4);
            CP_ASYNC16(db + so, Wb + (size_t)row * K + k0 + q * 4);
        }
    };

    float c[4][4][4];
#pragma unroll
    for (int i = 0; i < 4; ++i)
#pragma unroll
        for (int j = 0; j < 4; ++j)
#pragma unroll
            for (int r = 0; r < 4; ++r) c[i][j][r] = 0.f;

    load_tile(0, 0);
    CP_COMMIT();

    const int NKB = K / 16;   // 64
    for (int kb = 0; kb < NKB; ++kb) {
        const int buf = kb & 1;
        if (kb + 1 < NKB) {
            load_tile(kb + 1, buf ^ 1);
            CP_COMMIT();
            CP_WAIT1();
        } else {
            CP_WAIT0();
        }
        __syncthreads();

        const float* as = &As[buf][0];
        const float* bs = &Bs[buf][0];
#pragma unroll
        for (int ks = 0; ks < 2; ++ks) {
            const int k8 = ks * 8;
            uint32_t af[4][4], bf[4][2];
#pragma unroll
            for (int mt = 0; mt < 4; ++mt) {
                const int r0 = wm + mt * 16 + lr;
                af[mt][0] = f2tf(as[r0 * SA + k8 + lc]);
                af[mt][1] = f2tf(as[(r0 + 8) * SA + k8 + lc]);
                af[mt][2] = f2tf(as[r0 * SA + k8 + lc + 4]);
                af[mt][3] = f2tf(as[(r0 + 8) * SA + k8 + lc + 4]);
            }
#pragma unroll
            for (int nt = 0; nt < 4; ++nt) {
                const int n0 = wn + nt * 8 + lr;
                bf[nt][0] = f2tf(bs[n0 * SA + k8 + lc]);
                bf[nt][1] = f2tf(bs[n0 * SA + k8 + lc + 4]);
            }
#pragma unroll
            for (int mt = 0; mt < 4; ++mt)
#pragma unroll
                for (int nt = 0; nt < 4; ++nt)
                    mma_tf32(c[mt][nt], af[mt], bf[nt]);
        }
        __syncthreads();
    }

    // Epilogue: thread owns rows (wm+mt*16+lr, +8), cols (wn+nt*8+2*lc, +1)
#pragma unroll
    for (int mt = 0; mt < 4; ++mt) {
#pragma unroll
        for (int half = 0; half < 2; ++half) {
            const int row = bm + wm + mt * 16 + lr + half * 8;
#pragma unroll
            for (int nt = 0; nt < 4; ++nt) {
                const int col = bn + wn + nt * 8 + 2 * lc;
                const float v0 = c[mt][nt][half * 2 + 0];
                const float v1 = c[mt][nt][half * 2 + 1];
                if (MODE == 0) {
                    const int b = row >> 11, n = row & (NS - 1);
                    const int which = col >> 10;
                    const int rem = col & (Cc - 1);
                    const int h = rem >> 6, hd = rem & (HD - 1);
                    float* dst = (which == 0 ? g_q : which == 1 ? g_k : g_v)
                                 + (size_t)((b * Hh + h) * NS + n) * HD + hd;
                    float2 v = {v0, v1};
                    *(float2*)dst = v;
                } else {
                    float2 v = {v0 + bias[col], v1 + bias[col + 1]};
                    *(float2*)(Cout + (size_t)row * Ncol + col) = v;
                }
            }
        }
    }
}

// ---------------------------------------------------------------------------
// TF32 flash attention. 1 CTA = 256 threads (8 warps) handles one (b,h) and
// 128 q-rows; warp w owns q-rows [w*16, w*16+16). Per KV tile (64 rows):
// S = Q*K^T via mma (Q frags register-resident), online softmax in registers,
// P -> per-warp smem (pre-converted tf32 bits), O += P*V via mma.
// ---------------------------------------------------------------------------
constexpr int SK = 68;   // Ks stride (floats): conflict-free b-frag loads
constexpr int SV = 72;   // Vs stride: conflict-free b-frag loads
constexpr int SP = 68;   // Ps/Qs stride: conflict-free a-frag loads
constexpr int ATT_SMEM_FLOATS = 64 * SK + 64 * SV + 128 * SP + 64;
constexpr int ATT_SMEM = ATT_SMEM_FLOATS * 4;   // 70912 B (dynamic)

__global__ __launch_bounds__(256)
void attn_kernel(const float* __restrict__ mWin)
{
    extern __shared__ float sm[];
    float* Ks = sm;                    // [64][SK]
    float* Vs = Ks + 64 * SK;          // [64][SV]
    float* Ps = Vs + 64 * SV;          // [128][SP]  (doubles as Q staging)
    float* biasS = Ps + 128 * SP;      // [64]
    uint32_t* Psu = (uint32_t*)Ps;

    const int tid = threadIdx.x;
    const int w = tid >> 5, lane = tid & 31;
    const int lr = lane >> 2, lc = lane & 3;
    const int bh = blockIdx.y;
    const int b = bh >> 4, h = bh & (Hh - 1);
    const int qb = blockIdx.x * 128;

    // ---- stage Q tile [128][64] into Ps area, build register fragments ----
    {
        const float* qsrc = g_q + (size_t)(bh * NS + qb) * HD;
#pragma unroll
        for (int it = 0; it < 8; ++it) {
            const int idx = tid + it * 256;       // 0..2047
            const int row = idx >> 4, q4 = idx & 15;
            *(float4*)(Ps + row * SP + q4 * 4) =
                *(const float4*)(qsrc + (size_t)row * HD + q4 * 4);
        }
    }
    __syncthreads();

    uint32_t uq[8][4];
    {
        const int r0 = w * 16 + lr;
#pragma unroll
        for (int ks = 0; ks < 8; ++ks) {
            const int k8 = ks * 8;
            uq[ks][0] = f2tf(Ps[r0 * SP + k8 + lc] * SCALE);
            uq[ks][1] = f2tf(Ps[(r0 + 8) * SP + k8 + lc] * SCALE);
            uq[ks][2] = f2tf(Ps[r0 * SP + k8 + lc + 4] * SCALE);
            uq[ks][3] = f2tf(Ps[(r0 + 8) * SP + k8 + lc + 4] * SCALE);
        }
    }

    float o[8][4];
#pragma unroll
    for (int t = 0; t < 8; ++t)
#pragma unroll
        for (int r = 0; r < 4; ++r) o[t][r] = 0.f;
    float m0 = -INFINITY, m1 = -INFINITY, l0 = 0.f, l1 = 0.f;

    const float* kbase = g_k + (size_t)bh * NS * HD;
    const float* vbase = g_v + (size_t)bh * NS * HD;

    for (int kv0 = 0; kv0 < NS; kv0 += 64) {
        __syncthreads();   // previous tile's Ks/Vs reads complete
        // ---- load K/V tiles + bias ----
#pragma unroll
        for (int it = 0; it < 4; ++it) {
            const int idx = tid + it * 256;       // 0..1023
            const int row = idx >> 4, q4 = idx & 15;
            *(float4*)(Ks + row * SK + q4 * 4) =
                *(const float4*)(kbase + (size_t)(kv0 + row) * HD + q4 * 4);
            *(float4*)(Vs + row * SV + q4 * 4) =
                *(const float4*)(vbase + (size_t)(kv0 + row) * HD + q4 * 4);
        }
        if (tid < 64)
            biasS[tid] = mWin[b * NS + kv0 + tid] * 100.f - 100.f;
        __syncthreads();

        // ---- S = Q * K^T ----
        float s[8][4];
#pragma unroll
        for (int t = 0; t < 8; ++t)
#pragma unroll
            for (int r = 0; r < 4; ++r) s[t][r] = 0.f;
#pragma unroll
        for (int ks = 0; ks < 8; ++ks) {
            const int k8 = ks * 8;
            uint32_t kf[8][2];
#pragma unroll
            for (int nt = 0; nt < 8; ++nt) {
                const int n0 = nt * 8 + lr;
                kf[nt][0] = f2tf(Ks[n0 * SK + k8 + lc]);
                kf[nt][1] = f2tf(Ks[n0 * SK + k8 + lc + 4]);
            }
#pragma unroll
            for (int nt = 0; nt < 8; ++nt)
                mma_tf32(s[nt], uq[ks], kf[nt]);
        }

        // ---- bias + online softmax ----
        float mx0 = -INFINITY, mx1 = -INFINITY;
#pragma unroll
        for (int nt = 0; nt < 8; ++nt) {
            const int col = nt * 8 + 2 * lc;
            const float bi0 = biasS[col], bi1 = biasS[col + 1];
            s[nt][0] += bi0; s[nt][1] += bi1;
            s[nt][2] += bi0; s[nt][3] += bi1;
            mx0 = fmaxf(mx0, fmaxf(s[nt][0], s[nt][1]));
            mx1 = fmaxf(mx1, fmaxf(s[nt][2], s[nt][3]));
        }
        mx0 = fmaxf(mx0, __shfl_xor_sync(0xffffffffu, mx0, 1));
        mx0 = fmaxf(mx0, __shfl_xor_sync(0xffffffffu, mx0, 2));
        mx1 = fmaxf(mx1, __shfl_xor_sync(0xffffffffu, mx1, 1));
        mx1 = fmaxf(mx1, __shfl_xor_sync(0xffffffffu, mx1, 2));

        const float nm0 = fmaxf(m0, mx0), nm1 = fmaxf(m1, mx1);
        const float corr0 = __expf(m0 - nm0), corr1 = __expf(m1 - nm1);
        m0 = nm0; m1 = nm1;

        const int r0 = w * 16 + lr;
        float sum0 = 0.f, sum1 = 0.f;
#pragma unroll
        for (int nt = 0; nt < 8; ++nt) {
            const int col = nt * 8 + 2 * lc;
            const float p00 = __expf(s[nt][0] - m0);
            const float p01 = __expf(s[nt][1] - m0);
            const float p10 = __expf(s[nt][2] - m1);
            const float p11 = __expf(s[nt][3] - m1);
            sum0 += p00 + p01;
            sum1 += p10 + p11;
            uint2 w0 = {f2tf(p00), f2tf(p01)};
            uint2 w1 = {f2tf(p10), f2tf(p11)};
            *(uint2*)(Psu + r0 * SP + col) = w0;
            *(uint2*)(Psu + (r0 + 8) * SP + col) = w1;
            o[nt][0] *= corr0; o[nt][1] *= corr0;
            o[nt][2] *= corr1; o[nt][3] *= corr1;
        }
        sum0 += __shfl_xor_sync(0xffffffffu, sum0, 1);
        sum0 += __shfl_xor_sync(0xffffffffu, sum0, 2);
        sum1 += __shfl_xor_sync(0xffffffffu, sum1, 1);
        sum1 += __shfl_xor_sync(0xffffffffu, sum1, 2);
        l0 = l0 * corr0 + sum0;
        l1 = l1 * corr1 + sum1;
        __syncwarp();

        // ---- O += P * V ----
#pragma unroll
        for (int ks = 0; ks < 8; ++ks) {
            const int k8 = ks * 8;
            uint32_t pa[4];
            pa[0] = Psu[r0 * SP + k8 + lc];
            pa[1] = Psu[(r0 + 8) * SP + k8 + lc];
            pa[2] = Psu[r0 * SP + k8 + lc + 4];
            pa[3] = Psu[(r0 + 8) * SP + k8 + lc + 4];
            uint32_t vf[8][2];
#pragma unroll
            for (int nt = 0; nt < 8; ++nt) {
                const int n0 = nt * 8 + lr;
                vf[nt][0] = f2tf(Vs[(k8 + lc) * SV + n0]);
                vf[nt][1] = f2tf(Vs[(k8 + 4 + lc) * SV + n0]);
            }
#pragma unroll
            for (int nt = 0; nt < 8; ++nt)
                mma_tf32(o[nt], pa, vf[nt]);
        }
    }

    // ---- epilogue: O / l -> g_attn [B,N,C] at column block h*64 ----
    const float inv0 = 1.f / l0, inv1 = 1.f / l1;
    const int row0 = qb + w * 16 + lr;
    float* ob0 = g_attn + (size_t)(b * NS + row0) * Cc + h * HD;
    float* ob1 = g_attn + (size_t)(b * NS + row0 + 8) * Cc + h * HD;
#pragma unroll
    for (int nt = 0; nt < 8; ++nt) {
        const int col = nt * 8 + 2 * lc;
        float2 v0 = {o[nt][0] * inv0, o[nt][1] * inv0};
        float2 v1 = {o[nt][2] * inv1, o[nt][3] * inv1};
        *(float2*)(ob0 + col) = v0;
        *(float2*)(ob1 + col) = v1;
    }
}

// ---------------------------------------------------------------------------
// Launch: QKV (mma.sync tf32) -> attention (mma.sync tf32) -> proj (+bias)
// ---------------------------------------------------------------------------
extern "C" void kernel_launch(void* const* d_in, const int* in_sizes, int n_in,
                              void* d_out, int out_size)
{
    const float* x      = (const float*)d_in[0];
    const float* mWin   = (const float*)d_in[1];
    const float* w_qkv  = (const float*)d_in[2];
    const float* w_proj = (const float*)d_in[3];
    const float* b_proj = (const float*)d_in[4];
    float* out = (float*)d_out;

    cudaFuncSetAttribute(attn_kernel,
                         cudaFuncAttributeMaxDynamicSharedMemorySize, ATT_SMEM);

    // QKV projection: M=8192, N=3072, K=1024
    tgemm_kernel<0><<<dim3(3 * Cc / 128, Bb * NS / 128), 256>>>(
        x, w_qkv, nullptr, nullptr, Bb * NS, 3 * Cc, Cc);

    // Attention: (N/128 q-tiles, B*H), 8 warps x 16 q-rows = 128 rows/CTA
    attn_kernel<<<dim3(NS / 128, Bb * Hh), 256, ATT_SMEM>>>(mWin);

    // Output projection: M=8192, N=1024, K=1024, + bias
    tgemm_kernel<1><<<dim3(Cc / 128, Bb * NS / 128), 256>>>(
        nullptr, w_proj, b_proj, out, Bb * NS, Cc, Cc);
}